// round 2
// baseline (speedup 1.0000x reference)
#include <cuda_runtime.h>
#include <math.h>
#include <string.h>

// Problem constants
#define NN   1024
#define MUL  128
#define CH   128
#define RBq  20
#define RAq  19
#define DX   9     // (L1+1)^2 = (L2+1)^2
#define DZ   25    // (LZ+1)^2
#define MAXG 480

#define SCALE_IN  0.08838834764831845f   // 1/sqrt(128)
#define SCALE_OUT 0.08838834764831845f   // 1/sqrt(128)

// Sparse Gaunt table, passed by value as kernel parameter (constant memory).
struct GTab {
    int   start[DZ + 1];   // CSR-style segments per output d
    int   idx[MAXG];       // (d1 << 8) | d2
    float coef[MAXG];
};

// Scratch for linear_in results (static device arrays: allowed)
__device__ float g_xc[NN * CH * DX];
__device__ float g_yc[NN * CH * DX];

// ---------------------------------------------------------------------------
// Host: build the Gaunt table exactly as the reference quadrature defines it.
// Runs on every kernel_launch call (capture-time only; not in the timed graph
// replay path). Double precision throughout.
// ---------------------------------------------------------------------------
static double assoc_legendre_h(int l, int m, double x) {
    double pmm = 1.0;
    if (m > 0) {
        double df = 1.0;
        for (int i = 1; i < 2 * m; i += 2) df *= (double)i;
        pmm = ((m & 1) ? -1.0 : 1.0) * df * pow(1.0 - x * x, 0.5 * m);
    }
    if (l == m) return pmm;
    double pmmp1 = x * (2 * m + 1) * pmm;
    if (l == m + 1) return pmmp1;
    double p = pmmp1;
    for (int ll = m + 2; ll <= l; ++ll) {
        p = ((2 * ll - 1) * x * pmmp1 - (ll + m - 1) * pmm) / (ll - m);
        pmm = pmmp1; pmmp1 = p;
    }
    return pmmp1;
}

static void build_gtab(GTab* gt) {
    // Gauss-Legendre nodes/weights, n = 20 (Newton iteration, double precision)
    double ct[RBq], qw[RBq];
    const int n = RBq;
    for (int i = 0; i < n; ++i) {
        double z = cos(M_PI * (i + 0.75) / (n + 0.5));
        double pp = 1.0;
        for (int it = 0; it < 100; ++it) {
            double p1 = 1.0, p2 = 0.0;
            for (int j = 1; j <= n; ++j) {
                double p3 = p2; p2 = p1;
                p1 = ((2.0 * j - 1.0) * z * p2 - (j - 1.0) * p3) / (double)j;
            }
            pp = n * (z * p1 - p2) / (z * z - 1.0);
            double dz = p1 / pp;
            z -= dz;
            if (fabs(dz) < 1e-15) break;
        }
        ct[i] = z;
        qw[i] = 2.0 / ((1.0 - z * z) * pp * pp);
    }

    // Real orthonormal SH table Y[d][b][a], d < 25
    static double Y[DZ][RBq][RAq];
    for (int l = 0; l <= 4; ++l) {
        for (int m = -l; m <= l; ++m) {
            int am = m < 0 ? -m : m;
            double f1 = 1.0, f2 = 1.0;
            for (int i = 2; i <= l - am; ++i) f1 *= (double)i;
            for (int i = 2; i <= l + am; ++i) f2 *= (double)i;
            double nlm = sqrt((2.0 * l + 1.0) / (4.0 * M_PI) * f1 / f2);
            for (int b = 0; b < RBq; ++b) {
                double P = assoc_legendre_h(l, am, ct[b]);
                for (int a = 0; a < RAq; ++a) {
                    double alpha = 2.0 * M_PI * (double)a / (double)RAq;
                    double ang;
                    if (m == 0)      ang = 1.0;
                    else if (m > 0)  ang = sqrt(2.0) * cos(m * alpha);
                    else             ang = sqrt(2.0) * sin(am * alpha);
                    Y[l * l + l + m][b][a] = nlm * P * ang;
                }
            }
        }
    }

    // G[d][d1][d2] via the exact same quadrature; keep nonzeros (CSR by d)
    int cnt = 0;
    for (int d = 0; d < DZ; ++d) {
        gt->start[d] = cnt;
        for (int d1 = 0; d1 < DX; ++d1) {
            for (int d2 = 0; d2 < DX; ++d2) {
                double s = 0.0;
                for (int b = 0; b < RBq; ++b) {
                    double rs = 0.0;
                    for (int a = 0; a < RAq; ++a)
                        rs += Y[d][b][a] * Y[d1][b][a] * Y[d2][b][a];
                    s += rs * qw[b];
                }
                s *= 2.0 * M_PI / (double)RAq;
                if (fabs(s) > 1e-8 && cnt < MAXG) {
                    gt->idx[cnt]  = (d1 << 8) | d2;
                    gt->coef[cnt] = (float)s;
                    ++cnt;
                }
            }
        }
    }
    gt->start[DZ] = cnt;
    // zero-fill rest (deterministic param bytes)
    for (int k = cnt; k < MAXG; ++k) { gt->idx[k] = 0; gt->coef[k] = 0.0f; }
}

// ---------------------------------------------------------------------------
// Kernel 1: per-l linear_in for both x and y.
//   xc[n,c,d] = (1/sqrt(MUL)) * sum_m x[n,m,d] * wx[l(d),m,c]
// 4 nodes per CTA, 128 threads (thread = output channel c).
// ---------------------------------------------------------------------------
__global__ void __launch_bounds__(128) k_lin_in(
    const float* __restrict__ x, const float* __restrict__ y,
    const float* __restrict__ wx, const float* __restrict__ wy)
{
    __shared__ float xs[4 * MUL * 12];   // pad 9 -> 12 for float4 loads (24 KB)
    const int c  = threadIdx.x;
    const int n0 = blockIdx.x * 4;

    for (int pass = 0; pass < 2; ++pass) {
        const float* src = pass ? y    : x;
        const float* w   = pass ? wy   : wx;
        float*       dst = pass ? g_yc : g_xc;

        __syncthreads();
        // load 4 nodes of input into padded shared
        for (int i = c; i < 4 * MUL * DX; i += 128) {
            int j = i / (MUL * DX);
            int r = i - j * (MUL * DX);
            int m = r / DX;
            int d = r - m * DX;
            xs[(j * MUL + m) * 12 + d] = src[(size_t)(n0 + j) * (MUL * DX) + r];
        }
        __syncthreads();

        float acc[4][9];
        #pragma unroll
        for (int j = 0; j < 4; ++j)
            #pragma unroll
            for (int d = 0; d < 9; ++d) acc[j][d] = 0.0f;

        const float* wc = w + c;
        for (int m = 0; m < MUL; ++m) {
            float w0 = wc[(0 * MUL + m) * CH];
            float w1 = wc[(1 * MUL + m) * CH];
            float w2 = wc[(2 * MUL + m) * CH];
            #pragma unroll
            for (int j = 0; j < 4; ++j) {
                const float4* p = (const float4*)&xs[(j * MUL + m) * 12];
                float4 a = p[0];
                float4 b = p[1];
                float  e = xs[(j * MUL + m) * 12 + 8];
                acc[j][0] = fmaf(w0, a.x, acc[j][0]);
                acc[j][1] = fmaf(w1, a.y, acc[j][1]);
                acc[j][2] = fmaf(w1, a.z, acc[j][2]);
                acc[j][3] = fmaf(w1, a.w, acc[j][3]);
                acc[j][4] = fmaf(w2, b.x, acc[j][4]);
                acc[j][5] = fmaf(w2, b.y, acc[j][5]);
                acc[j][6] = fmaf(w2, b.z, acc[j][6]);
                acc[j][7] = fmaf(w2, b.w, acc[j][7]);
                acc[j][8] = fmaf(w2, e,   acc[j][8]);
            }
        }

        __syncthreads();
        // stage to shared ([j][c][9] linear) for coalesced global stores
        #pragma unroll
        for (int j = 0; j < 4; ++j)
            #pragma unroll
            for (int d = 0; d < 9; ++d)
                xs[(j * CH + c) * 9 + d] = acc[j][d] * SCALE_IN;
        __syncthreads();
        for (int i = c; i < 4 * CH * DX; i += 128)
            dst[(size_t)n0 * (CH * DX) + i] = xs[i];
    }
}

// ---------------------------------------------------------------------------
// Kernel 2: sparse Gaunt contraction + per-l linear_out.
//   z[c,d]  = sum_k G(d; d1,d2) xc[c,d1] yc[c,d2]
//   out[n,e,d] = (1/sqrt(CH)) * sum_c z[c,d] wz[l(d),c,e]
// 2 nodes per CTA, 128 threads.
// ---------------------------------------------------------------------------
__global__ void __launch_bounds__(128) k_gaunt_out(
    const float* __restrict__ wz, float* __restrict__ out, GTab gt)
{
    __shared__ float xcs[2 * CH * DX];     //  9216 B
    __shared__ float ycs[2 * CH * DX];     //  9216 B
    __shared__ float zs [2 * CH * 28];     // 28672 B (pad 25 -> 28 for float4)

    const int t  = threadIdx.x;
    const int n0 = blockIdx.x * 2;

    for (int i = t; i < 2 * CH * DX; i += 128) {
        xcs[i] = g_xc[(size_t)n0 * CH * DX + i];
        ycs[i] = g_yc[(size_t)n0 * CH * DX + i];
    }
    __syncthreads();

    // ---- Phase B: sparse Gaunt, thread = channel c, both nodes ----
    {
        const int c = t;
        const float* xr0 = &xcs[c * DX];
        const float* xr1 = &xcs[CH * DX + c * DX];
        const float* yr0 = &ycs[c * DX];
        const float* yr1 = &ycs[CH * DX + c * DX];
        for (int d = 0; d < DZ; ++d) {
            float z0 = 0.0f, z1 = 0.0f;
            const int e0 = gt.start[d], e1 = gt.start[d + 1];
            for (int k = e0; k < e1; ++k) {
                const int   id = gt.idx[k];
                const float cf = gt.coef[k];
                const int d1 = id >> 8;
                const int d2 = id & 255;
                z0 = fmaf(cf, xr0[d1] * yr0[d2], z0);
                z1 = fmaf(cf, xr1[d1] * yr1[d2], z1);
            }
            zs[c * 28 + d]           = z0;
            zs[CH * 28 + c * 28 + d] = z1;
        }
    }
    __syncthreads();

    // ---- Phase C: linear_out, thread = output channel e ----
    const int e = t;
    float acc[2][25];
    #pragma unroll
    for (int j = 0; j < 2; ++j)
        #pragma unroll
        for (int d = 0; d < 25; ++d) acc[j][d] = 0.0f;

    const int LOF[25] = {0, 1,1,1, 2,2,2,2,2, 3,3,3,3,3,3,3, 4,4,4,4,4,4,4,4,4};

    const float* wze = wz + e;
    for (int cc = 0; cc < CH; ++cc) {
        float wv[5];
        #pragma unroll
        for (int l = 0; l < 5; ++l) wv[l] = wze[(size_t)(l * CH + cc) * CH];
        #pragma unroll
        for (int j = 0; j < 2; ++j) {
            float zv[25];
            const float4* zp = (const float4*)&zs[(j * CH + cc) * 28];
            #pragma unroll
            for (int q = 0; q < 6; ++q) {
                float4 v = zp[q];
                zv[4 * q + 0] = v.x; zv[4 * q + 1] = v.y;
                zv[4 * q + 2] = v.z; zv[4 * q + 3] = v.w;
            }
            zv[24] = zs[(j * CH + cc) * 28 + 24];
            #pragma unroll
            for (int d = 0; d < 25; ++d)
                acc[j][d] = fmaf(wv[LOF[d]], zv[d], acc[j][d]);
        }
    }

    __syncthreads();   // all zs reads done; reuse zs as packed staging buffer
    #pragma unroll
    for (int j = 0; j < 2; ++j)
        #pragma unroll
        for (int d = 0; d < 25; ++d)
            zs[j * CH * DZ + e * DZ + d] = acc[j][d] * SCALE_OUT;
    __syncthreads();
    for (int i = t; i < 2 * CH * DZ; i += 128)
        out[(size_t)n0 * CH * DZ + i] = zs[i];
}

// ---------------------------------------------------------------------------
extern "C" void kernel_launch(void* const* d_in, const int* in_sizes, int n_in,
                              void* d_out, int out_size)
{
    const float* x  = (const float*)d_in[0];
    const float* y  = (const float*)d_in[1];
    const float* wx = (const float*)d_in[2];
    const float* wy = (const float*)d_in[3];
    const float* wz = (const float*)d_in[4];
    float* out = (float*)d_out;

    GTab gt;
    build_gtab(&gt);

    k_lin_in<<<NN / 4, 128>>>(x, y, wx, wy);
    k_gaunt_out<<<NN / 2, 128>>>(wz, out, gt);
}